// round 15
// baseline (speedup 1.0000x reference)
#include <cuda_runtime.h>
#include <math.h>

#define Bx 32
#define Nx 500
#define T0x 13
#define Ex 2000
#define EHx 300
#define Cx 40

typedef unsigned long long ull;
#define FMA2(d,a,b) asm("fma.rn.f32x2 %0, %1, %2, %0;" : "+l"(d) : "l"(a), "l"(b))
#define PACK2(d,x)  asm("mov.b64 %0, {%1,%1};" : "=l"(d) : "f"(x))
#define UNPK2(lo,hi,v) asm("mov.b64 {%0,%1}, %2;" : "=f"(lo), "=f"(hi) : "l"(v))

// ---------------- scratch ----------------
__device__ float g_Xa[(long)Bx*Cx*13*Nx];
__device__ float g_Xb[(long)Bx*Cx*11*Nx];
__device__ float g_H [(long)Bx*7*Cx*11*Nx];
__device__ float g_G [(long)Bx*Cx*11*Nx];
__device__ float g_S1[(long)Bx*320*7*Nx];
__device__ float g_SK[(long)Bx*120*7*Nx];
__device__ float g_SKW[320*120];
__device__ float g_SKB[320];
__device__ float g_E1[(long)Bx*640*7*Nx];
__device__ float g_nin[Bx*T0x*Nx];
__device__ double g_part[256];
__device__ float g_part2[1280];
__device__ float g_mstd[2];
__device__ float g_adp[Nx*Nx];
__device__ float g_adp2[Nx*Nx];
__device__ float g_adpc[Nx*1000];
__device__ float g_xm[Bx*Cx*Nx];
__device__ float g_scf[Bx*Ex], g_scb[Bx*Ex];
__device__ float g_uf[Bx*EHx], g_ub[Bx*EHx];
__device__ float g_ef[Bx*Ex], g_eb[Bx*Ex];
__device__ float g_bn[2*Cx];
__device__ int   g_islast[Ex];
__device__ float g_diagf[Nx], g_diagb[Nx];
__device__ int   g_cntd[Nx], g_cnts[Nx], g_offd[Nx+1], g_offs[Nx+1];
__device__ int   g_dnode[Ex], g_deid[Ex]; __device__ float g_dw[Ex];
__device__ int   g_snode[Ex], g_seid[Ex]; __device__ float g_sw[Ex];
__device__ float g_WT[3*Cx*7*Cx];

static inline long divup(long a, long b){ return (a+b-1)/b; }

// ---------------- input stats ----------------
__global__ void k_instats1(const float* __restrict__ in, int n){
  __shared__ double ss[256], sq[256];
  int tid = threadIdx.x; double s=0, q=0;
  for (int i = blockIdx.x*256+tid; i < n; i += gridDim.x*256){ float v=in[i]; s+=v; q+=(double)v*v; }
  ss[tid]=s; sq[tid]=q; __syncthreads();
  for (int o=128;o>0;o>>=1){ if(tid<o){ ss[tid]+=ss[tid+o]; sq[tid]+=sq[tid+o]; } __syncthreads(); }
  if (!tid){ g_part[blockIdx.x]=ss[0]; g_part[128+blockIdx.x]=sq[0]; }
}
__global__ void k_instats2(int nblk, int n){
  __shared__ double ss[128], sq[128];
  int tid = threadIdx.x;
  ss[tid] = (tid<nblk)? g_part[tid]:0.0; sq[tid] = (tid<nblk)? g_part[128+tid]:0.0;
  __syncthreads();
  for (int o=64;o>0;o>>=1){ if(tid<o){ ss[tid]+=ss[tid+o]; sq[tid]+=sq[tid+o]; } __syncthreads(); }
  if (!tid){ double m=ss[0]/n, v=sq[0]/n-m*m; g_mstd[0]=(float)m; g_mstd[1]=(float)rsqrt(v+1e-5); }
}
__global__ void k_norm(const float* __restrict__ in){
  int i = blockIdx.x*256+threadIdx.x; if (i >= Bx*T0x*Nx) return;
  int t = i%T0x; int r = i/T0x; int n = r%Nx; int b = r/Nx;
  g_nin[(b*T0x+t)*Nx+n] = (in[(b*Nx+n)*T0x+t]-g_mstd[0])*g_mstd[1];
}
__global__ void k_start(const float* __restrict__ sw, const float* __restrict__ sb){
  long i = blockIdx.x*256L+threadIdx.x; long tot=(long)Bx*Cx*T0x*Nx; if (i>=tot) return;
  int n = i%Nx; long r=i/Nx; int t = r%T0x; r/=T0x; int c = r%Cx; int b = r/Cx;
  g_Xa[i] = sw[c]*g_nin[(b*T0x+t)*Nx+n] + sb[c];
}
// ---------------- adp ----------------
__global__ void k_adpmm(const float* __restrict__ v1, const float* __restrict__ v2){
  int i = blockIdx.x*256+threadIdx.x; if (i>=Nx*Nx) return;
  int n=i/Nx, m=i%Nx; float s=0.f;
  #pragma unroll
  for (int k=0;k<10;k++) s += v1[n*10+k]*v2[k*Nx+m];
  g_adp[i] = fmaxf(s,0.f);
}
__global__ void k_softmax(){
  int n = blockIdx.x, tid = threadIdx.x;
  __shared__ float red[256];
  float mx=-1e30f;
  for (int m=tid;m<Nx;m+=256) mx=fmaxf(mx,g_adp[n*Nx+m]);
  red[tid]=mx; __syncthreads();
  for (int o=128;o>0;o>>=1){ if(tid<o) red[tid]=fmaxf(red[tid],red[tid+o]); __syncthreads(); }
  mx=red[0]; __syncthreads();
  float s=0.f;
  for (int m=tid;m<Nx;m+=256) s+=expf(g_adp[n*Nx+m]-mx);
  red[tid]=s; __syncthreads();
  for (int o=128;o>0;o>>=1){ if(tid<o) red[tid]+=red[tid+o]; __syncthreads(); }
  float inv=1.f/red[0];
  for (int m=tid;m<Nx;m+=256) g_adp[n*Nx+m]=expf(g_adp[n*Nx+m]-mx)*inv;
}
__global__ void k_adpcat(){
  int i = blockIdx.x*256+threadIdx.x; if (i>=Nx*1000) return;
  int r=i/1000, c=i%1000;
  g_adpc[i] = (c<Nx)? g_adp[r*Nx+c] : g_adp2[r*Nx+c-Nx];
}
// ---------------- edge structures ----------------
__global__ void k_islast(const int* __restrict__ idx){
  int e = blockIdx.x*128+threadIdx.x; if (e>=Ex) return;
  int a=idx[e], b=idx[Ex+e]; int last=1;
  for (int f=e+1;f<Ex;f++) if (idx[f]==a && idx[Ex+f]==b){ last=0; break; }
  g_islast[e]=last;
}
__global__ void k_keep(const int* __restrict__ idx, const float* __restrict__ Af, const float* __restrict__ Ab){
  int m = blockIdx.x*128+threadIdx.x; if (m>=Nx) return;
  float keep=1.f;
  for (int e=0;e<Ex;e++) if (idx[e]==m && idx[Ex+e]==m){ keep=0.f; break; }
  g_diagf[m]=keep*Af[m*Nx+m]; g_diagb[m]=keep*Ab[m*Nx+m];
  g_cntd[m]=0; g_cnts[m]=0;
}
__global__ void k_count(const int* __restrict__ idx){
  int e = blockIdx.x*128+threadIdx.x; if (e>=Ex) return;
  if (g_islast[e]){ atomicAdd(&g_cntd[idx[Ex+e]],1); atomicAdd(&g_cnts[idx[e]],1); }
}
__global__ void k_scan(){
  int s=0; for (int i=0;i<Nx;i++){ g_offd[i]=s; s+=g_cntd[i]; } g_offd[Nx]=s;
  s=0;     for (int i=0;i<Nx;i++){ g_offs[i]=s; s+=g_cnts[i]; } g_offs[Nx]=s;
}
__global__ void k_fill(const int* __restrict__ idx, const float* __restrict__ Af, const float* __restrict__ Ab){
  int m = blockIdx.x*64+threadIdx.x; if (m>=Nx) return;
  int pd=g_offd[m], ps=g_offs[m];
  for (int e=0;e<Ex;e++){
    if (!g_islast[e]) continue;
    int i0=idx[e], i1=idx[Ex+e];
    if (i1==m){ g_dnode[pd]=i0; g_deid[pd]=e; g_dw[pd]=Af[i0*Nx+m]; pd++; }
    if (i0==m){ g_snode[ps]=i1; g_seid[ps]=e; g_sw[ps]=Ab[i1*Nx+m]; ps++; }
  }
}
__global__ void k_transW(const float* __restrict__ W){
  int i = blockIdx.x*256+threadIdx.x; if (i>=3*Cx*7*Cx) return;
  int c = i%(7*Cx); int r = i/(7*Cx); int o = r%Cx; int blk = r/Cx;
  g_WT[i] = W[(blk*7*Cx + c)*Cx + o];
}
// ---------------- skip concat prep ----------------
__global__ void k_skprep(const float* __restrict__ skw, const float* __restrict__ skb){
  int i = blockIdx.x*256+threadIdx.x;
  if (i < 320*120){
    int m=i/120, k=i%120; int blk=k/40, c=k%40;
    g_SKW[i] = skw[(blk*320+m)*40+c];
  }
  if (i < 320) g_SKB[i] = skb[i]+skb[320+i]+skb[640+i];
}
// ---------------- per-block small ----------------
__global__ void k_xmean(const float* __restrict__ X, int Told){
  int i = blockIdx.x*256+threadIdx.x; if (i>=Bx*Cx*Nx) return;
  int n=i%Nx; int r=i/Nx; int c=r%Cx; int b=r/Cx;
  const float* p = X + ((long)(b*Cx+c))*Told*Nx + n;
  float s=0.f; for (int t=0;t<Told;t++) s += p[(long)t*Nx];
  g_xm[i] = s/Told;
}
__global__ void k_escore(const int* __restrict__ idx, const float* __restrict__ vsf,
    const float* __restrict__ vdf, const float* __restrict__ vsb, const float* __restrict__ vdb){
  int i = blockIdx.x*128+threadIdx.x; if (i>=Bx*Ex) return;
  int e=i%Ex, b=i/Ex; int i0=idx[e], i1=idx[Ex+e];
  float sf=0.f, sb=0.f;
  for (int c=0;c<Cx;c++){
    float s=g_xm[(b*Cx+c)*Nx+i0], d=g_xm[(b*Cx+c)*Nx+i1];
    sf += s*vsf[c]+d*vdf[c]; sb += s*vsb[c]+d*vdb[c];
  }
  g_scf[i]=sf; g_scb[i]=sb;
}
__global__ void k_edge1(const float* __restrict__ G0){
  int i = blockIdx.x*128+threadIdx.x; if (i>=Bx*EHx) return;
  int h=i%EHx, b=i/EHx;
  float uf=0.f, ub=0.f;
  for (int e=0;e<Ex;e++){ float g=G0[e*EHx+h]; uf+=g_scf[b*Ex+e]*g; ub+=g_scb[b*Ex+e]*g; }
  g_uf[i]=uf; g_ub[i]=ub;
}
__global__ void k_edge2(const float* __restrict__ G1, const float* __restrict__ wf, const float* __restrict__ wb){
  int i = blockIdx.x*128+threadIdx.x; if (i>=Bx*Ex) return;
  int e=i%Ex, b=i/Ex;
  float f=0.f, bb=0.f;
  for (int h=0;h<EHx;h++){ float g=G1[h*Ex+e]; f+=g_uf[b*EHx+h]*wf[h]*g; bb+=g_ub[b*EHx+h]*wb[h]*g; }
  g_ef[i]=1.f/(1.f+expf(-f)); g_eb[i]=1.f/(1.f+expf(-bb));
}
// ---------------- dconv: smem-tiled ----------------
__global__ void k_dconv2(const float* __restrict__ X, int Told,
    const float* __restrict__ Wf, const float* __restrict__ bf,
    const float* __restrict__ Wg, const float* __restrict__ bg, int Tb){
  __shared__ float sx0[Cx][64], sx2[Cx][64];
  __shared__ float swf[Cx][80], swg[Cx][80];
  int b = blockIdx.x, t = blockIdx.y, n0 = blockIdx.z*64;
  int tid = threadIdx.x;
  for (int i=tid; i<Cx*80; i+=256){ swf[i/80][i%80]=Wf[i]; swg[i/80][i%80]=Wg[i]; }
  for (int i=tid; i<Cx*64; i+=256){
    int c=i/64, n=i%64; int nn=n0+n;
    float v0=0.f, v2=0.f;
    if (nn<Nx){
      const float* xb = X + ((long)(b*Cx+c)*Told + t)*Nx;
      v0 = xb[nn]; v2 = xb[2*Nx+nn];
    }
    sx0[c][n]=v0; sx2[c][n]=v2;
  }
  __syncthreads();
  int nl = tid&63, oq = tid>>6;
  float f[10], g[10];
  #pragma unroll
  for (int i=0;i<10;i++){ int o=oq+i*4; f[i]=bf[o]; g[i]=bg[o]; }
  #pragma unroll 4
  for (int c=0;c<Cx;c++){
    float x0=sx0[c][nl], x2=sx2[c][nl];
    #pragma unroll
    for (int i=0;i<10;i++){
      int o=oq+i*4;
      f[i] += swf[o][c*2]*x0 + swf[o][c*2+1]*x2;
      g[i] += swg[o][c*2]*x0 + swg[o][c*2+1]*x2;
    }
  }
  int nn = n0+nl;
  if (nn<Nx){
    #pragma unroll
    for (int i=0;i<10;i++){
      int o=oq+i*4;
      g_H[(((long)b*7*Cx+o)*Tb+t)*Nx + nn] = tanhf(f[i])*(1.f/(1.f+expf(-g[i])));
    }
  }
}
// ---------------- fused fwd+bwd sparse hop ----------------
__global__ void k_shop2(int Tb, int inF, int outF, int inB, int outB){
  long i = blockIdx.x*256L+threadIdx.x; long tot=(long)Bx*Cx*Tb*Nx; if (i>=tot) return;
  int m=i%Nx; long r=i/Nx; int t=r%Tb; r/=Tb; int c=r%Cx; int b=r/Cx;
  long base = ((long)b*7*Cx + c)*Tb*Nx + (long)t*Nx;
  const float* gf = g_ef + (long)b*Ex;
  const float* gb = g_eb + (long)b*Ex;
  const float* iF = g_H + (long)inF*Tb*Nx;
  const float* iB = g_H + (long)inB*Tb*Nx;
  float vf = g_diagf[m]*iF[base+m];
  for (int j=g_offd[m]; j<g_offd[m+1]; j++)
    vf += gf[g_deid[j]]*g_dw[j]*iF[base+g_dnode[j]];
  float vb = g_diagb[m]*iB[base+m];
  for (int j=g_offs[m]; j<g_offs[m+1]; j++)
    vb += gb[g_seid[j]]*g_sw[j]*iB[base+g_snode[j]];
  g_H[(long)outF*Tb*Nx + base + m] = vf;
  g_H[(long)outB*Tb*Nx + base + m] = vb;
}
// ---------------- gconv: 40x128 tile, W resident in smem ----------------
__global__ void k_gconv(const float* __restrict__ W, float* __restrict__ Gout,
                        int TN, const float* __restrict__ bias, const float* __restrict__ Hbase){
  __shared__ float Ws[Cx*7*Cx];
  __shared__ float Bs[8][128];
  int b = blockIdx.z; int col0 = blockIdx.x*128;
  const float* Hb = Hbase + (long)b*7*Cx*TN;
  float* Gb = Gout + (long)b*Cx*TN;
  int tid = threadIdx.x;
  for (int i=tid;i<Cx*7*Cx;i+=256) Ws[i]=W[i];
  int tx = tid&63, ty = tid>>6;
  int bn = tid&127, bk = (tid>>7)*4;
  bool ncol = (col0+bn < TN);
  ull acc[10] = {};
  for (int k0=0; k0<7*Cx; k0+=8){
    #pragma unroll
    for (int j=0;j<4;j++)
      Bs[bk+j][bn] = ncol? Hb[(long)(k0+bk+j)*TN + col0+bn] : 0.f;
    __syncthreads();
    #pragma unroll
    for (int kk=0;kk<8;kk++){
      ull bb = *reinterpret_cast<const ull*>(&Bs[kk][tx*2]);
      #pragma unroll
      for (int i=0;i<10;i++){
        float a = Ws[(ty+i*4)*7*Cx + k0+kk];
        ull a2; PACK2(a2,a);
        FMA2(acc[i],a2,bb);
      }
    }
    __syncthreads();
  }
  int n = col0+tx*2;
  #pragma unroll
  for (int i=0;i<10;i++){
    int r = ty+i*4;
    float lo,hi; UNPK2(lo,hi,acc[i]);
    if (n<TN)   Gb[(long)r*TN+n]   = lo + bias[r];
    if (n+1<TN) Gb[(long)r*TN+n+1] = hi + bias[r];
  }
}
// ---------------- 128x128 GEMM: f32x2, 2-stage smem DB, A pre-packed (a,a) ----------------
__global__ void k_gemm128(const float* __restrict__ A, const float* __restrict__ B, float* __restrict__ C,
    int M, int N, int K, long sA, long sB, long sC, int ldB,
    const float* __restrict__ bias, const float* __restrict__ acc,
    long sAcc, int ldAcc, int act, float* __restrict__ C2, int nsplit){
  int bz = blockIdx.z;
  A += (long)bz*sA; B += (long)bz*sB; C += (long)bz*sC;
  float* C2p = C2? C2 + (long)bz*sC : (float*)0;
  int row0 = blockIdx.y*128, col0 = blockIdx.x*128;
  __shared__ ull As2[2][8][128];
  __shared__ float Bs[2][8][128];
  int tid = threadIdx.x, tx = tid&15, ty = tid>>4;
  ull av[8][4] = {};
  int am = tid>>1, akq = (tid&1)*4;
  int bn = tid&127, bk4 = (tid>>7)*4;
  int m = row0+am;
  bool ncol = (col0+bn < N);
  float4 ra; float rb[4];
  {
    int k = akq;
    if (m < M && k+3 < K) ra = *reinterpret_cast<const float4*>(A + (long)m*K + k);
    else {
      ra.x = (m<M && k  <K)? A[(long)m*K+k  ] : 0.f;
      ra.y = (m<M && k+1<K)? A[(long)m*K+k+1] : 0.f;
      ra.z = (m<M && k+2<K)? A[(long)m*K+k+2] : 0.f;
      ra.w = (m<M && k+3<K)? A[(long)m*K+k+3] : 0.f;
    }
    #pragma unroll
    for (int j=0;j<4;j++) rb[j] = (bk4+j<K && ncol)? B[(long)(bk4+j)*ldB + col0+bn] : 0.f;
    ull p;
    PACK2(p,ra.x); As2[0][akq  ][am]=p;
    PACK2(p,ra.y); As2[0][akq+1][am]=p;
    PACK2(p,ra.z); As2[0][akq+2][am]=p;
    PACK2(p,ra.w); As2[0][akq+3][am]=p;
    #pragma unroll
    for (int j=0;j<4;j++) Bs[0][bk4+j][bn] = rb[j];
  }
  __syncthreads();
  int buf = 0;
  for (int k0=0; k0<K; k0+=8){
    bool nxt = (k0+8 < K);
    if (nxt){
      int k = k0+8+akq;
      if (m < M && k+3 < K) ra = *reinterpret_cast<const float4*>(A + (long)m*K + k);
      else {
        ra.x = (m<M && k  <K)? A[(long)m*K+k  ] : 0.f;
        ra.y = (m<M && k+1<K)? A[(long)m*K+k+1] : 0.f;
        ra.z = (m<M && k+2<K)? A[(long)m*K+k+2] : 0.f;
        ra.w = (m<M && k+3<K)? A[(long)m*K+k+3] : 0.f;
      }
      #pragma unroll
      for (int j=0;j<4;j++){
        int kk = k0+8+bk4+j;
        rb[j] = (kk<K && ncol)? B[(long)kk*ldB + col0+bn] : 0.f;
      }
    }
    #pragma unroll
    for (int kk=0;kk<8;kk++){
      ull a2[8], bb[4];
      #pragma unroll
      for (int i=0;i<8;i++) a2[i] = As2[buf][kk][ty+i*16];
      #pragma unroll
      for (int j=0;j<4;j++) bb[j] = *reinterpret_cast<const ull*>(&Bs[buf][kk][tx*2+j*32]);
      #pragma unroll
      for (int i=0;i<8;i++)
        #pragma unroll
        for (int j=0;j<4;j++) FMA2(av[i][j], a2[i], bb[j]);
    }
    if (nxt){
      ull p;
      PACK2(p,ra.x); As2[buf^1][akq  ][am]=p;
      PACK2(p,ra.y); As2[buf^1][akq+1][am]=p;
      PACK2(p,ra.z); As2[buf^1][akq+2][am]=p;
      PACK2(p,ra.w); As2[buf^1][akq+3][am]=p;
      #pragma unroll
      for (int j=0;j<4;j++) Bs[buf^1][bk4+j][bn] = rb[j];
    }
    __syncthreads();
    buf ^= 1;
  }
  #pragma unroll
  for (int i=0;i<8;i++){
    int mm=row0+ty+i*16; if (mm>=M) continue;
    float bv = bias? bias[mm] : 0.f;
    #pragma unroll
    for (int j=0;j<4;j++){
      int n=col0+tx*2+j*32;
      if (n>=N) continue;
      float lo, hi; UNPK2(lo,hi,av[i][j]);
      float* dst; int ldC; int nn;
      if (C2p && n>=nsplit){ dst=C2p; nn=n-nsplit; ldC=N-nsplit; }
      else { dst=C; nn=n; ldC = C2p? nsplit : N; }
      {
        float v = lo + bv;
        if (acc) v += acc[(long)bz*sAcc + (long)mm*ldAcc + n];
        if (act==1) v = v>0.f? v : 0.01f*v;
        dst[(long)mm*ldC+nn] = v;
      }
      if (n+1<N){
        float v = hi + bv;
        if (acc) v += acc[(long)bz*sAcc + (long)mm*ldAcc + n+1];
        if (act==1) v = v>0.f? v : 0.01f*v;
        dst[(long)mm*ldC+nn+1] = v;
      }
    }
  }
}
// ---------------- BN: parallel 2-stage stats ----------------
__global__ void k_bnstats1(const float* __restrict__ X, int Tb){
  int c = blockIdx.x, chunk = blockIdx.y, tid = threadIdx.x;
  __shared__ float ss[256], sq[256];
  long per = (long)Tb*Nx, tot = (long)Bx*per;
  long lo = tot*chunk/16, hi = tot*(chunk+1)/16;
  float s=0.f, q=0.f;
  for (long i=lo+tid;i<hi;i+=256){
    int b = (int)(i/per); long r = i%per;
    float v = X[((long)b*Cx+c)*per + r];
    s+=v; q+=v*v;
  }
  ss[tid]=s; sq[tid]=q; __syncthreads();
  for (int o=128;o>0;o>>=1){ if(tid<o){ ss[tid]+=ss[tid+o]; sq[tid]+=sq[tid+o]; } __syncthreads(); }
  if (!tid){ g_part2[c*16+chunk]=ss[0]; g_part2[640+c*16+chunk]=sq[0]; }
}
__global__ void k_bnstats2(int Tb){
  int c = threadIdx.x; if (c>=Cx) return;
  float s=0.f, q=0.f;
  for (int j=0;j<16;j++){ s+=g_part2[c*16+j]; q+=g_part2[640+c*16+j]; }
  long tot = (long)Bx*Tb*Nx;
  float m = s/tot, v = q/tot - m*m;
  g_bn[c]=m; g_bn[Cx+c]=rsqrtf(v+1e-5f);
}
__global__ void k_bnapply1(const float* __restrict__ G, const float* __restrict__ Xres, int Told,
    float* __restrict__ Xn, int Tb, const float* __restrict__ ga, const float* __restrict__ be){
  long i = blockIdx.x*256L+threadIdx.x; long tot=(long)Bx*Cx*Tb*Nx; if (i>=tot) return;
  int n=i%Nx; long r=i/Nx; int t=r%Tb; r/=Tb; int c=r%Cx; int b=r/Cx;
  float v = ga[c]*(G[i]-g_bn[c])*g_bn[Cx+c] + be[c];
  Xn[i] = v + Xres[((long)(b*Cx+c)*Told + t+2)*Nx + n];
}
__global__ void k_bnapply2(float* __restrict__ X, int Tb, const float* __restrict__ ga, const float* __restrict__ be){
  long i = blockIdx.x*256L+threadIdx.x; long tot=(long)Bx*Cx*Tb*Nx; if (i>=tot) return;
  long per=(long)Tb*Nx; int c = (int)((i/per)%Cx);
  X[i] = ga[c]*(X[i]-g_bn[c])*g_bn[Cx+c] + be[c];
}
// ---------------- stash truncated activations ----------------
__global__ void k_skcopy(const float* __restrict__ X, int Tb, int slot){
  long i = blockIdx.x*256L+threadIdx.x;
  long tot = (long)Bx*Cx*7*Nx; if (i>=tot) return;
  int n = (int)(i % (7*Nx)); long r = i/(7*Nx); int c = (int)(r%Cx); int b = (int)(r/Cx);
  g_SK[((long)b*120 + slot*Cx + c)*7*Nx + n] = X[((long)(b*Cx+c)*Tb + (Tb-7))*Nx + n];
}
// ---------------- end2 ----------------
__global__ void k_end2(const float* __restrict__ W, const float* __restrict__ bb, float* __restrict__ out){
  __shared__ float Ws[12*640];
  int b = blockIdx.x, t = blockIdx.y;
  int tid = threadIdx.x;
  for (int i=tid;i<12*640;i+=256) Ws[i]=W[i];
  __syncthreads();
  const float* e = g_E1 + (long)b*640*7*Nx + (long)t*Nx;
  for (int n=tid; n<Nx; n+=256){
    float acc[12];
    #pragma unroll
    for (int o=0;o<12;o++) acc[o]=bb[o];
    #pragma unroll 4
    for (int k=0;k<640;k++){
      float ev = e[(long)k*7*Nx + n];
      #pragma unroll
      for (int o=0;o<12;o++) acc[o] += ev*Ws[o*640+k];
    }
    #pragma unroll
    for (int o=0;o<12;o++)
      out[((long)(b*12+o)*Nx + n)*7 + t] = acc[o];
  }
}

extern "C" void kernel_launch(void* const* d_in, const int* in_sizes, int n_in,
                              void* d_out, int out_size){
  const float* in  =(const float*)d_in[0];
  const float* Af  =(const float*)d_in[1];
  const float* Ab  =(const float*)d_in[2];
  const int*   idx =(const int*)  d_in[3];
  const float* G0  =(const float*)d_in[4];
  const float* G1  =(const float*)d_in[5];
  const float* nv1 =(const float*)d_in[6];
  const float* nv2 =(const float*)d_in[7];
  const float* wef =(const float*)d_in[8];
  const float* web =(const float*)d_in[9];
  const float* vsf =(const float*)d_in[10];
  const float* vdf =(const float*)d_in[11];
  const float* vsb =(const float*)d_in[12];
  const float* vdb =(const float*)d_in[13];
  const float* sw  =(const float*)d_in[14];
  const float* sb  =(const float*)d_in[15];
  const float* fw  =(const float*)d_in[16];
  const float* fb  =(const float*)d_in[17];
  const float* gw  =(const float*)d_in[18];
  const float* gb  =(const float*)d_in[19];
  const float* gcw =(const float*)d_in[20];
  const float* gcb =(const float*)d_in[21];
  const float* bgg =(const float*)d_in[22];
  const float* bgb =(const float*)d_in[23];
  const float* bng =(const float*)d_in[24];
  const float* bnb =(const float*)d_in[25];
  const float* skw =(const float*)d_in[26];
  const float* skb =(const float*)d_in[27];
  const float* e1w =(const float*)d_in[28];
  const float* e1b =(const float*)d_in[29];
  const float* e2w =(const float*)d_in[30];
  const float* e2b =(const float*)d_in[31];
  float* out = (float*)d_out;

  float *Xa,*Xb,*H,*G,*S1,*SK,*SKW,*SKB,*E1,*ADP,*ADP2,*ADPC,*WT;
  cudaGetSymbolAddress((void**)&Xa, g_Xa);
  cudaGetSymbolAddress((void**)&Xb, g_Xb);
  cudaGetSymbolAddress((void**)&H,  g_H);
  cudaGetSymbolAddress((void**)&G,  g_G);
  cudaGetSymbolAddress((void**)&S1, g_S1);
  cudaGetSymbolAddress((void**)&SK, g_SK);
  cudaGetSymbolAddress((void**)&SKW,g_SKW);
  cudaGetSymbolAddress((void**)&SKB,g_SKB);
  cudaGetSymbolAddress((void**)&E1, g_E1);
  cudaGetSymbolAddress((void**)&ADP,g_adp);
  cudaGetSymbolAddress((void**)&ADP2,g_adp2);
  cudaGetSymbolAddress((void**)&ADPC,g_adpc);
  cudaGetSymbolAddress((void**)&WT, g_WT);

  int tin = Bx*T0x*Nx;
  k_instats1<<<128,256>>>(in, tin);
  k_instats2<<<1,128>>>(128, tin);
  k_norm<<<(int)divup(tin,256),256>>>(in);
  { long t=(long)Bx*Cx*T0x*Nx; k_start<<<(int)divup(t,256),256>>>(sw, sb); }
  k_adpmm<<<(int)divup(Nx*Nx,256),256>>>(nv1,nv2);
  k_softmax<<<Nx,256>>>();
  // ADP2 = ADP @ ADP, then concat [ADP | ADP2]
  {
    dim3 gr((unsigned)divup(Nx,128),(unsigned)divup(Nx,128),1);
    k_gemm128<<<gr,256>>>(ADP, ADP, ADP2, Nx, Nx, Nx, 0,0,0, Nx, 0,0,0,0,0, 0,0);
  }
  k_adpcat<<<(int)divup(Nx*1000,256),256>>>();
  k_islast<<<(int)divup(Ex,128),128>>>(idx);
  k_keep<<<(int)divup(Nx,128),128>>>(idx, Af, Ab);
  k_count<<<(int)divup(Ex,128),128>>>(idx);
  k_scan<<<1,1>>>();
  k_fill<<<(int)divup(Nx,64),64>>>(idx, Af, Ab);
  k_transW<<<(int)divup(3*Cx*7*Cx,256),256>>>(gcw);
  k_skprep<<<(int)divup(320*120,256),256>>>(skw, skb);

  float* Xcur = Xa; float* Xnext = Xb;
  int Told = 13;
  const long SKN = 7L*Nx;
  for (int blk=0; blk<3; blk++){
    int Tb = Told-2;
    long TN = (long)Tb*Nx;
    long totd = (long)Bx*Cx*TN;
    k_xmean<<<(int)divup(Bx*Cx*Nx,256),256>>>(Xcur, Told);
    k_escore<<<(int)divup(Bx*Ex,128),128>>>(idx, vsf+blk*Cx, vdf+blk*Cx, vsb+blk*Cx, vdb+blk*Cx);
    k_edge1<<<(int)divup(Bx*EHx,128),128>>>(G0);
    k_edge2<<<(int)divup(Bx*Ex,128),128>>>(G1, wef, web);
    {
      dim3 gr(Bx, Tb, (unsigned)divup(Nx,64));
      k_dconv2<<<gr,256>>>(Xcur, Told, fw+blk*Cx*Cx*2, fb+blk*Cx,
                           gw+blk*Cx*Cx*2, gb+blk*Cx, Tb);
    }
    k_shop2<<<(int)divup(totd,256),256>>>(Tb, 0, 40, 0, 120);
    k_shop2<<<(int)divup(totd,256),256>>>(Tb, 40, 80, 120, 160);
    { // fused adp hops: [x@ADP | x@ADP2] in one GEMM
      dim3 gr((unsigned)divup(1000,128),(unsigned)divup(Cx*Tb,128),Bx);
      k_gemm128<<<gr,256>>>(H, ADPC, H+200*TN, Cx*Tb, 1000, Nx,
                            7*Cx*TN, 0, 7*Cx*TN, 1000, 0,0,0,0,0,
                            H+240*TN, 500);
    }
    {
      dim3 gr((unsigned)divup(TN,128),1,Bx);
      k_gconv<<<gr,256>>>(WT+blk*Cx*7*Cx, G, (int)TN, gcb+blk*Cx, H);
    }
    { dim3 gs(Cx,16); k_bnstats1<<<gs,256>>>(G, Tb); }
    k_bnstats2<<<1,64>>>(Tb);
    k_bnapply1<<<(int)divup(totd,256),256>>>(G, Xcur, Told, Xnext, Tb, bgg+blk*Cx, bgb+blk*Cx);
    { dim3 gs(Cx,16); k_bnstats1<<<gs,256>>>(Xnext, Tb); }
    k_bnstats2<<<1,64>>>(Tb);
    k_bnapply2<<<(int)divup(totd,256),256>>>(Xnext, Tb, bng+blk*Cx, bnb+blk*Cx);
    k_skcopy<<<(int)divup((long)Bx*Cx*SKN,256),256>>>(Xnext, Tb, blk);
    float* tmp = Xcur; Xcur = Xnext; Xnext = tmp;
    Told = Tb;
  }
  { // fused skip: leaky( SKW @ SK + SKB ), K=120
    dim3 gr((unsigned)divup(SKN,128),(unsigned)divup(320,128),Bx);
    k_gemm128<<<gr,256>>>(SKW, SK, S1, 320, (int)SKN, 120,
                          0, 120L*SKN, 320L*SKN, (int)SKN, SKB, 0,0,0, 1, 0,0);
  }
  { // end1
    dim3 gr((unsigned)divup(SKN,128),(unsigned)divup(640,128),Bx);
    k_gemm128<<<gr,256>>>(e1w, S1, E1, 640, (int)SKN, 320,
                          0, 320L*SKN, 640L*SKN, (int)SKN, e1b, 0,0,0, 1, 0,0);
  }
  k_end2<<<dim3(Bx,7),256>>>(e2w, e2b, out);
}

// round 16
// speedup vs baseline: 1.0426x; 1.0426x over previous
#include <cuda_runtime.h>
#include <math.h>

#define Bx 32
#define Nx 500
#define T0x 13
#define Ex 2000
#define EHx 300
#define Cx 40

typedef unsigned long long ull;
#define FMA2(d,a,b) asm("fma.rn.f32x2 %0, %1, %2, %0;" : "+l"(d) : "l"(a), "l"(b))
#define PACK2(d,x)  asm("mov.b64 %0, {%1,%1};" : "=l"(d) : "f"(x))
#define UNPK2(lo,hi,v) asm("mov.b64 {%0,%1}, %2;" : "=f"(lo), "=f"(hi) : "l"(v))

// ---------------- scratch ----------------
__device__ float g_Xa[(long)Bx*Cx*13*Nx];
__device__ float g_Xb[(long)Bx*Cx*11*Nx];
__device__ float g_H [(long)Bx*7*Cx*11*Nx];
__device__ float g_G [(long)Bx*Cx*11*Nx];
__device__ float g_S1[(long)Bx*320*7*Nx];
__device__ float g_SK[(long)Bx*120*7*Nx];
__device__ float g_SKW[320*120];
__device__ float g_SKB[320];
__device__ float g_E1[(long)Bx*640*7*Nx];
__device__ float g_nin[Bx*T0x*Nx];
__device__ double g_part[256];
__device__ float g_part2[1280];
__device__ float g_mstd[2];
__device__ float g_adp[Nx*Nx];
__device__ float g_adp2[Nx*Nx];
__device__ float g_adpc[Nx*1000];
__device__ float g_xm[Bx*Cx*Nx];
__device__ float g_scf[Bx*Ex], g_scb[Bx*Ex];
__device__ float g_uf[Bx*EHx], g_ub[Bx*EHx];
__device__ float g_ef[Bx*Ex], g_eb[Bx*Ex];
__device__ float g_bn[2*Cx];
__device__ int   g_islast[Ex];
__device__ float g_diagf[Nx], g_diagb[Nx];
__device__ int   g_cntd[Nx], g_cnts[Nx], g_offd[Nx+1], g_offs[Nx+1];
__device__ int   g_dnode[Ex], g_deid[Ex]; __device__ float g_dw[Ex];
__device__ int   g_snode[Ex], g_seid[Ex]; __device__ float g_sw[Ex];
__device__ float g_WT[3*Cx*7*Cx];

static inline long divup(long a, long b){ return (a+b-1)/b; }

// ---------------- input stats ----------------
__global__ void k_instats1(const float* __restrict__ in, int n){
  __shared__ double ss[256], sq[256];
  int tid = threadIdx.x; double s=0, q=0;
  for (int i = blockIdx.x*256+tid; i < n; i += gridDim.x*256){ float v=in[i]; s+=v; q+=(double)v*v; }
  ss[tid]=s; sq[tid]=q; __syncthreads();
  for (int o=128;o>0;o>>=1){ if(tid<o){ ss[tid]+=ss[tid+o]; sq[tid]+=sq[tid+o]; } __syncthreads(); }
  if (!tid){ g_part[blockIdx.x]=ss[0]; g_part[128+blockIdx.x]=sq[0]; }
}
__global__ void k_instats2(int nblk, int n){
  __shared__ double ss[128], sq[128];
  int tid = threadIdx.x;
  ss[tid] = (tid<nblk)? g_part[tid]:0.0; sq[tid] = (tid<nblk)? g_part[128+tid]:0.0;
  __syncthreads();
  for (int o=64;o>0;o>>=1){ if(tid<o){ ss[tid]+=ss[tid+o]; sq[tid]+=sq[tid+o]; } __syncthreads(); }
  if (!tid){ double m=ss[0]/n, v=sq[0]/n-m*m; g_mstd[0]=(float)m; g_mstd[1]=(float)rsqrt(v+1e-5); }
}
__global__ void k_norm(const float* __restrict__ in){
  int i = blockIdx.x*256+threadIdx.x; if (i >= Bx*T0x*Nx) return;
  int t = i%T0x; int r = i/T0x; int n = r%Nx; int b = r/Nx;
  g_nin[(b*T0x+t)*Nx+n] = (in[(b*Nx+n)*T0x+t]-g_mstd[0])*g_mstd[1];
}
__global__ void k_start(const float* __restrict__ sw, const float* __restrict__ sb){
  long i = blockIdx.x*256L+threadIdx.x; long tot=(long)Bx*Cx*T0x*Nx; if (i>=tot) return;
  int n = i%Nx; long r=i/Nx; int t = r%T0x; r/=T0x; int c = r%Cx; int b = r/Cx;
  g_Xa[i] = sw[c]*g_nin[(b*T0x+t)*Nx+n] + sb[c];
}
// ---------------- adp ----------------
__global__ void k_adpmm(const float* __restrict__ v1, const float* __restrict__ v2){
  int i = blockIdx.x*256+threadIdx.x; if (i>=Nx*Nx) return;
  int n=i/Nx, m=i%Nx; float s=0.f;
  #pragma unroll
  for (int k=0;k<10;k++) s += v1[n*10+k]*v2[k*Nx+m];
  g_adp[i] = fmaxf(s,0.f);
}
__global__ void k_softmax(){
  int n = blockIdx.x, tid = threadIdx.x;
  __shared__ float red[256];
  float mx=-1e30f;
  for (int m=tid;m<Nx;m+=256) mx=fmaxf(mx,g_adp[n*Nx+m]);
  red[tid]=mx; __syncthreads();
  for (int o=128;o>0;o>>=1){ if(tid<o) red[tid]=fmaxf(red[tid],red[tid+o]); __syncthreads(); }
  mx=red[0]; __syncthreads();
  float s=0.f;
  for (int m=tid;m<Nx;m+=256) s+=expf(g_adp[n*Nx+m]-mx);
  red[tid]=s; __syncthreads();
  for (int o=128;o>0;o>>=1){ if(tid<o) red[tid]+=red[tid+o]; __syncthreads(); }
  float inv=1.f/red[0];
  for (int m=tid;m<Nx;m+=256) g_adp[n*Nx+m]=expf(g_adp[n*Nx+m]-mx)*inv;
}
__global__ void k_adpcat(){
  int i = blockIdx.x*256+threadIdx.x; if (i>=Nx*1000) return;
  int r=i/1000, c=i%1000;
  g_adpc[i] = (c<Nx)? g_adp[r*Nx+c] : g_adp2[r*Nx+c-Nx];
}
// ---------------- edge structures ----------------
__global__ void k_islast(const int* __restrict__ idx){
  int e = blockIdx.x*128+threadIdx.x; if (e>=Ex) return;
  int a=idx[e], b=idx[Ex+e]; int last=1;
  for (int f=e+1;f<Ex;f++) if (idx[f]==a && idx[Ex+f]==b){ last=0; break; }
  g_islast[e]=last;
}
__global__ void k_keep(const int* __restrict__ idx, const float* __restrict__ Af, const float* __restrict__ Ab){
  int m = blockIdx.x*128+threadIdx.x; if (m>=Nx) return;
  float keep=1.f;
  for (int e=0;e<Ex;e++) if (idx[e]==m && idx[Ex+e]==m){ keep=0.f; break; }
  g_diagf[m]=keep*Af[m*Nx+m]; g_diagb[m]=keep*Ab[m*Nx+m];
  g_cntd[m]=0; g_cnts[m]=0;
}
__global__ void k_count(const int* __restrict__ idx){
  int e = blockIdx.x*128+threadIdx.x; if (e>=Ex) return;
  if (g_islast[e]){ atomicAdd(&g_cntd[idx[Ex+e]],1); atomicAdd(&g_cnts[idx[e]],1); }
}
__global__ void k_scan(){
  int s=0; for (int i=0;i<Nx;i++){ g_offd[i]=s; s+=g_cntd[i]; } g_offd[Nx]=s;
  s=0;     for (int i=0;i<Nx;i++){ g_offs[i]=s; s+=g_cnts[i]; } g_offs[Nx]=s;
}
__global__ void k_fill(const int* __restrict__ idx, const float* __restrict__ Af, const float* __restrict__ Ab){
  int m = blockIdx.x*64+threadIdx.x; if (m>=Nx) return;
  int pd=g_offd[m], ps=g_offs[m];
  for (int e=0;e<Ex;e++){
    if (!g_islast[e]) continue;
    int i0=idx[e], i1=idx[Ex+e];
    if (i1==m){ g_dnode[pd]=i0; g_deid[pd]=e; g_dw[pd]=Af[i0*Nx+m]; pd++; }
    if (i0==m){ g_snode[ps]=i1; g_seid[ps]=e; g_sw[ps]=Ab[i1*Nx+m]; ps++; }
  }
}
__global__ void k_transW(const float* __restrict__ W){
  int i = blockIdx.x*256+threadIdx.x; if (i>=3*Cx*7*Cx) return;
  int c = i%(7*Cx); int r = i/(7*Cx); int o = r%Cx; int blk = r/Cx;
  g_WT[i] = W[(blk*7*Cx + c)*Cx + o];
}
// ---------------- skip concat prep ----------------
__global__ void k_skprep(const float* __restrict__ skw, const float* __restrict__ skb){
  int i = blockIdx.x*256+threadIdx.x;
  if (i < 320*120){
    int m=i/120, k=i%120; int blk=k/40, c=k%40;
    g_SKW[i] = skw[(blk*320+m)*40+c];
  }
  if (i < 320) g_SKB[i] = skb[i]+skb[320+i]+skb[640+i];
}
// ---------------- per-block small ----------------
__global__ void k_xmean(const float* __restrict__ X, int Told){
  int i = blockIdx.x*256+threadIdx.x; if (i>=Bx*Cx*Nx) return;
  int n=i%Nx; int r=i/Nx; int c=r%Cx; int b=r/Cx;
  const float* p = X + ((long)(b*Cx+c))*Told*Nx + n;
  float s=0.f; for (int t=0;t<Told;t++) s += p[(long)t*Nx];
  g_xm[i] = s/Told;
}
__global__ void k_escore(const int* __restrict__ idx, const float* __restrict__ vsf,
    const float* __restrict__ vdf, const float* __restrict__ vsb, const float* __restrict__ vdb){
  int i = blockIdx.x*128+threadIdx.x; if (i>=Bx*Ex) return;
  int e=i%Ex, b=i/Ex; int i0=idx[e], i1=idx[Ex+e];
  float sf=0.f, sb=0.f;
  for (int c=0;c<Cx;c++){
    float s=g_xm[(b*Cx+c)*Nx+i0], d=g_xm[(b*Cx+c)*Nx+i1];
    sf += s*vsf[c]+d*vdf[c]; sb += s*vsb[c]+d*vdb[c];
  }
  g_scf[i]=sf; g_scb[i]=sb;
}
__global__ void k_edge1(const float* __restrict__ G0){
  int i = blockIdx.x*128+threadIdx.x; if (i>=Bx*EHx) return;
  int h=i%EHx, b=i/EHx;
  float uf=0.f, ub=0.f;
  for (int e=0;e<Ex;e++){ float g=G0[e*EHx+h]; uf+=g_scf[b*Ex+e]*g; ub+=g_scb[b*Ex+e]*g; }
  g_uf[i]=uf; g_ub[i]=ub;
}
__global__ void k_edge2(const float* __restrict__ G1, const float* __restrict__ wf, const float* __restrict__ wb){
  int i = blockIdx.x*128+threadIdx.x; if (i>=Bx*Ex) return;
  int e=i%Ex, b=i/Ex;
  float f=0.f, bb=0.f;
  for (int h=0;h<EHx;h++){ float g=G1[h*Ex+e]; f+=g_uf[b*EHx+h]*wf[h]*g; bb+=g_ub[b*EHx+h]*wb[h]*g; }
  g_ef[i]=1.f/(1.f+expf(-f)); g_eb[i]=1.f/(1.f+expf(-bb));
}
// ---------------- dconv: smem-tiled ----------------
__global__ void k_dconv2(const float* __restrict__ X, int Told,
    const float* __restrict__ Wf, const float* __restrict__ bf,
    const float* __restrict__ Wg, const float* __restrict__ bg, int Tb){
  __shared__ float sx0[Cx][64], sx2[Cx][64];
  __shared__ float swf[Cx][80], swg[Cx][80];
  int b = blockIdx.x, t = blockIdx.y, n0 = blockIdx.z*64;
  int tid = threadIdx.x;
  for (int i=tid; i<Cx*80; i+=256){ swf[i/80][i%80]=Wf[i]; swg[i/80][i%80]=Wg[i]; }
  for (int i=tid; i<Cx*64; i+=256){
    int c=i/64, n=i%64; int nn=n0+n;
    float v0=0.f, v2=0.f;
    if (nn<Nx){
      const float* xb = X + ((long)(b*Cx+c)*Told + t)*Nx;
      v0 = xb[nn]; v2 = xb[2*Nx+nn];
    }
    sx0[c][n]=v0; sx2[c][n]=v2;
  }
  __syncthreads();
  int nl = tid&63, oq = tid>>6;
  float f[10], g[10];
  #pragma unroll
  for (int i=0;i<10;i++){ int o=oq+i*4; f[i]=bf[o]; g[i]=bg[o]; }
  #pragma unroll 4
  for (int c=0;c<Cx;c++){
    float x0=sx0[c][nl], x2=sx2[c][nl];
    #pragma unroll
    for (int i=0;i<10;i++){
      int o=oq+i*4;
      f[i] += swf[o][c*2]*x0 + swf[o][c*2+1]*x2;
      g[i] += swg[o][c*2]*x0 + swg[o][c*2+1]*x2;
    }
  }
  int nn = n0+nl;
  if (nn<Nx){
    #pragma unroll
    for (int i=0;i<10;i++){
      int o=oq+i*4;
      g_H[(((long)b*7*Cx+o)*Tb+t)*Nx + nn] = tanhf(f[i])*(1.f/(1.f+expf(-g[i])));
    }
  }
}
// ---------------- fused fwd+bwd sparse hop ----------------
__global__ void k_shop2(int Tb, int inF, int outF, int inB, int outB){
  long i = blockIdx.x*256L+threadIdx.x; long tot=(long)Bx*Cx*Tb*Nx; if (i>=tot) return;
  int m=i%Nx; long r=i/Nx; int t=r%Tb; r/=Tb; int c=r%Cx; int b=r/Cx;
  long base = ((long)b*7*Cx + c)*Tb*Nx + (long)t*Nx;
  const float* gf = g_ef + (long)b*Ex;
  const float* gb = g_eb + (long)b*Ex;
  const float* iF = g_H + (long)inF*Tb*Nx;
  const float* iB = g_H + (long)inB*Tb*Nx;
  float vf = g_diagf[m]*iF[base+m];
  for (int j=g_offd[m]; j<g_offd[m+1]; j++)
    vf += gf[g_deid[j]]*g_dw[j]*iF[base+g_dnode[j]];
  float vb = g_diagb[m]*iB[base+m];
  for (int j=g_offs[m]; j<g_offs[m+1]; j++)
    vb += gb[g_seid[j]]*g_sw[j]*iB[base+g_snode[j]];
  g_H[(long)outF*Tb*Nx + base + m] = vf;
  g_H[(long)outB*Tb*Nx + base + m] = vb;
}
// ---------------- gconv: 40x128 tile, W resident in smem ----------------
__global__ void k_gconv(const float* __restrict__ W, float* __restrict__ Gout,
                        int TN, const float* __restrict__ bias, const float* __restrict__ Hbase){
  __shared__ float Ws[Cx*7*Cx];
  __shared__ float Bs[8][128];
  int b = blockIdx.z; int col0 = blockIdx.x*128;
  const float* Hb = Hbase + (long)b*7*Cx*TN;
  float* Gb = Gout + (long)b*Cx*TN;
  int tid = threadIdx.x;
  for (int i=tid;i<Cx*7*Cx;i+=256) Ws[i]=W[i];
  int tx = tid&63, ty = tid>>6;
  int bn = tid&127, bk = (tid>>7)*4;
  bool ncol = (col0+bn < TN);
  ull acc[10] = {};
  for (int k0=0; k0<7*Cx; k0+=8){
    #pragma unroll
    for (int j=0;j<4;j++)
      Bs[bk+j][bn] = ncol? Hb[(long)(k0+bk+j)*TN + col0+bn] : 0.f;
    __syncthreads();
    #pragma unroll
    for (int kk=0;kk<8;kk++){
      ull bb = *reinterpret_cast<const ull*>(&Bs[kk][tx*2]);
      #pragma unroll
      for (int i=0;i<10;i++){
        float a = Ws[(ty+i*4)*7*Cx + k0+kk];
        ull a2; PACK2(a2,a);
        FMA2(acc[i],a2,bb);
      }
    }
    __syncthreads();
  }
  int n = col0+tx*2;
  #pragma unroll
  for (int i=0;i<10;i++){
    int r = ty+i*4;
    float lo,hi; UNPK2(lo,hi,acc[i]);
    if (n<TN)   Gb[(long)r*TN+n]   = lo + bias[r];
    if (n+1<TN) Gb[(long)r*TN+n+1] = hi + bias[r];
  }
}
// ---------------- 128x128 GEMM: f32x2, 2-stage smem DB, ldB, split-C ----------------
__global__ void __launch_bounds__(256,2)
k_gemm128(const float* __restrict__ A, const float* __restrict__ B, float* __restrict__ C,
    int M, int N, int K, long sA, long sB, long sC, int ldB,
    const float* __restrict__ bias, const float* __restrict__ acc,
    long sAcc, int ldAcc, int act, float* __restrict__ C2, int nsplit){
  int bz = blockIdx.z;
  A += (long)bz*sA; B += (long)bz*sB; C += (long)bz*sC;
  float* C2p = C2? C2 + (long)bz*sC : (float*)0;
  int row0 = blockIdx.y*128, col0 = blockIdx.x*128;
  __shared__ float As[2][8][128], Bs[2][8][128];
  int tid = threadIdx.x, tx = tid&15, ty = tid>>4;
  ull av[8][4] = {};
  int am = tid>>1, akq = (tid&1)*4;
  int bn = tid&127, bk4 = (tid>>7)*4;
  int m = row0+am;
  bool ncol = (col0+bn < N);
  float4 ra; float rb[4];
  {
    int k = akq;
    if (m < M && k+3 < K) ra = *reinterpret_cast<const float4*>(A + (long)m*K + k);
    else {
      ra.x = (m<M && k  <K)? A[(long)m*K+k  ] : 0.f;
      ra.y = (m<M && k+1<K)? A[(long)m*K+k+1] : 0.f;
      ra.z = (m<M && k+2<K)? A[(long)m*K+k+2] : 0.f;
      ra.w = (m<M && k+3<K)? A[(long)m*K+k+3] : 0.f;
    }
    #pragma unroll
    for (int j=0;j<4;j++) rb[j] = (bk4+j<K && ncol)? B[(long)(bk4+j)*ldB + col0+bn] : 0.f;
    As[0][akq  ][am]=ra.x; As[0][akq+1][am]=ra.y;
    As[0][akq+2][am]=ra.z; As[0][akq+3][am]=ra.w;
    #pragma unroll
    for (int j=0;j<4;j++) Bs[0][bk4+j][bn] = rb[j];
  }
  __syncthreads();
  int buf = 0;
  for (int k0=0; k0<K; k0+=8){
    bool nxt = (k0+8 < K);
    if (nxt){
      int k = k0+8+akq;
      if (m < M && k+3 < K) ra = *reinterpret_cast<const float4*>(A + (long)m*K + k);
      else {
        ra.x = (m<M && k  <K)? A[(long)m*K+k  ] : 0.f;
        ra.y = (m<M && k+1<K)? A[(long)m*K+k+1] : 0.f;
        ra.z = (m<M && k+2<K)? A[(long)m*K+k+2] : 0.f;
        ra.w = (m<M && k+3<K)? A[(long)m*K+k+3] : 0.f;
      }
      #pragma unroll
      for (int j=0;j<4;j++){
        int kk = k0+8+bk4+j;
        rb[j] = (kk<K && ncol)? B[(long)kk*ldB + col0+bn] : 0.f;
      }
    }
    #pragma unroll
    for (int kk=0;kk<8;kk++){
      ull a2[8], bb[4];
      #pragma unroll
      for (int i=0;i<8;i++){ float a=As[buf][kk][ty+i*16]; PACK2(a2[i],a); }
      #pragma unroll
      for (int j=0;j<4;j++) bb[j] = *reinterpret_cast<const ull*>(&Bs[buf][kk][tx*2+j*32]);
      #pragma unroll
      for (int i=0;i<8;i++)
        #pragma unroll
        for (int j=0;j<4;j++) FMA2(av[i][j], a2[i], bb[j]);
    }
    if (nxt){
      As[buf^1][akq  ][am]=ra.x; As[buf^1][akq+1][am]=ra.y;
      As[buf^1][akq+2][am]=ra.z; As[buf^1][akq+3][am]=ra.w;
      #pragma unroll
      for (int j=0;j<4;j++) Bs[buf^1][bk4+j][bn] = rb[j];
    }
    __syncthreads();
    buf ^= 1;
  }
  #pragma unroll
  for (int i=0;i<8;i++){
    int mm=row0+ty+i*16; if (mm>=M) continue;
    float bv = bias? bias[mm] : 0.f;
    #pragma unroll
    for (int j=0;j<4;j++){
      int n=col0+tx*2+j*32;
      if (n>=N) continue;
      float lo, hi; UNPK2(lo,hi,av[i][j]);
      float* dst; int ldC; int nn;
      if (C2p && n>=nsplit){ dst=C2p; nn=n-nsplit; ldC=N-nsplit; }
      else { dst=C; nn=n; ldC = C2p? nsplit : N; }
      {
        float v = lo + bv;
        if (acc) v += acc[(long)bz*sAcc + (long)mm*ldAcc + n];
        if (act==1) v = v>0.f? v : 0.01f*v;
        dst[(long)mm*ldC+nn] = v;
      }
      if (n+1<N){
        float v = hi + bv;
        if (acc) v += acc[(long)bz*sAcc + (long)mm*ldAcc + n+1];
        if (act==1) v = v>0.f? v : 0.01f*v;
        dst[(long)mm*ldC+nn+1] = v;
      }
    }
  }
}
// ---------------- BN: parallel 2-stage stats ----------------
__global__ void k_bnstats1(const float* __restrict__ X, int Tb){
  int c = blockIdx.x, chunk = blockIdx.y, tid = threadIdx.x;
  __shared__ float ss[256], sq[256];
  long per = (long)Tb*Nx, tot = (long)Bx*per;
  long lo = tot*chunk/16, hi = tot*(chunk+1)/16;
  float s=0.f, q=0.f;
  for (long i=lo+tid;i<hi;i+=256){
    int b = (int)(i/per); long r = i%per;
    float v = X[((long)b*Cx+c)*per + r];
    s+=v; q+=v*v;
  }
  ss[tid]=s; sq[tid]=q; __syncthreads();
  for (int o=128;o>0;o>>=1){ if(tid<o){ ss[tid]+=ss[tid+o]; sq[tid]+=sq[tid+o]; } __syncthreads(); }
  if (!tid){ g_part2[c*16+chunk]=ss[0]; g_part2[640+c*16+chunk]=sq[0]; }
}
__global__ void k_bnstats2(int Tb){
  int c = threadIdx.x; if (c>=Cx) return;
  float s=0.f, q=0.f;
  for (int j=0;j<16;j++){ s+=g_part2[c*16+j]; q+=g_part2[640+c*16+j]; }
  long tot = (long)Bx*Tb*Nx;
  float m = s/tot, v = q/tot - m*m;
  g_bn[c]=m; g_bn[Cx+c]=rsqrtf(v+1e-5f);
}
__global__ void k_bnapply1(const float* __restrict__ G, const float* __restrict__ Xres, int Told,
    float* __restrict__ Xn, int Tb, const float* __restrict__ ga, const float* __restrict__ be){
  long i = blockIdx.x*256L+threadIdx.x; long tot=(long)Bx*Cx*Tb*Nx; if (i>=tot) return;
  int n=i%Nx; long r=i/Nx; int t=r%Tb; r/=Tb; int c=r%Cx; int b=r/Cx;
  float v = ga[c]*(G[i]-g_bn[c])*g_bn[Cx+c] + be[c];
  Xn[i] = v + Xres[((long)(b*Cx+c)*Told + t+2)*Nx + n];
}
// bnapply2 with fused skip-copy of the last 7 time-steps
__global__ void k_bnapply2(float* __restrict__ X, int Tb, const float* __restrict__ ga,
    const float* __restrict__ be, int slot){
  long i = blockIdx.x*256L+threadIdx.x; long tot=(long)Bx*Cx*Tb*Nx; if (i>=tot) return;
  int n=i%Nx; long r=i/Nx; int t=r%Tb; r/=Tb; int c=r%Cx; int b=r/Cx;
  float v = ga[c]*(X[i]-g_bn[c])*g_bn[Cx+c] + be[c];
  X[i] = v;
  int toff = t-(Tb-7);
  if (toff >= 0)
    g_SK[((long)b*120 + slot*Cx + c)*7*Nx + (long)toff*Nx + n] = v;
}
// ---------------- end2 ----------------
__global__ void k_end2(const float* __restrict__ W, const float* __restrict__ bb, float* __restrict__ out){
  __shared__ float Ws[12*640];
  int b = blockIdx.x, t = blockIdx.y;
  int tid = threadIdx.x;
  for (int i=tid;i<12*640;i+=256) Ws[i]=W[i];
  __syncthreads();
  const float* e = g_E1 + (long)b*640*7*Nx + (long)t*Nx;
  for (int n=tid; n<Nx; n+=256){
    float acc[12];
    #pragma unroll
    for (int o=0;o<12;o++) acc[o]=bb[o];
    #pragma unroll 4
    for (int k=0;k<640;k++){
      float ev = e[(long)k*7*Nx + n];
      #pragma unroll
      for (int o=0;o<12;o++) acc[o] += ev*Ws[o*640+k];
    }
    #pragma unroll
    for (int o=0;o<12;o++)
      out[((long)(b*12+o)*Nx + n)*7 + t] = acc[o];
  }
}

extern "C" void kernel_launch(void* const* d_in, const int* in_sizes, int n_in,
                              void* d_out, int out_size){
  const float* in  =(const float*)d_in[0];
  const float* Af  =(const float*)d_in[1];
  const float* Ab  =(const float*)d_in[2];
  const int*   idx =(const int*)  d_in[3];
  const float* G0  =(const float*)d_in[4];
  const float* G1  =(const float*)d_in[5];
  const float* nv1 =(const float*)d_in[6];
  const float* nv2 =(const float*)d_in[7];
  const float* wef =(const float*)d_in[8];
  const float* web =(const float*)d_in[9];
  const float* vsf =(const float*)d_in[10];
  const float* vdf =(const float*)d_in[11];
  const float* vsb =(const float*)d_in[12];
  const float* vdb =(const float*)d_in[13];
  const float* sw  =(const float*)d_in[14];
  const float* sb  =(const float*)d_in[15];
  const float* fw  =(const float*)d_in[16];
  const float* fb  =(const float*)d_in[17];
  const float* gw  =(const float*)d_in[18];
  const float* gb  =(const float*)d_in[19];
  const float* gcw =(const float*)d_in[20];
  const float* gcb =(const float*)d_in[21];
  const float* bgg =(const float*)d_in[22];
  const float* bgb =(const float*)d_in[23];
  const float* bng =(const float*)d_in[24];
  const float* bnb =(const float*)d_in[25];
  const float* skw =(const float*)d_in[26];
  const float* skb =(const float*)d_in[27];
  const float* e1w =(const float*)d_in[28];
  const float* e1b =(const float*)d_in[29];
  const float* e2w =(const float*)d_in[30];
  const float* e2b =(const float*)d_in[31];
  float* out = (float*)d_out;

  float *Xa,*Xb,*H,*G,*S1,*SK,*SKW,*SKB,*E1,*ADP,*ADP2,*ADPC,*WT;
  cudaGetSymbolAddress((void**)&Xa, g_Xa);
  cudaGetSymbolAddress((void**)&Xb, g_Xb);
  cudaGetSymbolAddress((void**)&H,  g_H);
  cudaGetSymbolAddress((void**)&G,  g_G);
  cudaGetSymbolAddress((void**)&S1, g_S1);
  cudaGetSymbolAddress((void**)&SK, g_SK);
  cudaGetSymbolAddress((void**)&SKW,g_SKW);
  cudaGetSymbolAddress((void**)&SKB,g_SKB);
  cudaGetSymbolAddress((void**)&E1, g_E1);
  cudaGetSymbolAddress((void**)&ADP,g_adp);
  cudaGetSymbolAddress((void**)&ADP2,g_adp2);
  cudaGetSymbolAddress((void**)&ADPC,g_adpc);
  cudaGetSymbolAddress((void**)&WT, g_WT);

  int tin = Bx*T0x*Nx;
  k_instats1<<<128,256>>>(in, tin);
  k_instats2<<<1,128>>>(128, tin);
  k_norm<<<(int)divup(tin,256),256>>>(in);
  { long t=(long)Bx*Cx*T0x*Nx; k_start<<<(int)divup(t,256),256>>>(sw, sb); }
  k_adpmm<<<(int)divup(Nx*Nx,256),256>>>(nv1,nv2);
  k_softmax<<<Nx,256>>>();
  // ADP2 = ADP @ ADP, then concat [ADP | ADP2]
  {
    dim3 gr((unsigned)divup(Nx,128),(unsigned)divup(Nx,128),1);
    k_gemm128<<<gr,256>>>(ADP, ADP, ADP2, Nx, Nx, Nx, 0,0,0, Nx, 0,0,0,0,0, 0,0);
  }
  k_adpcat<<<(int)divup(Nx*1000,256),256>>>();
  k_islast<<<(int)divup(Ex,128),128>>>(idx);
  k_keep<<<(int)divup(Nx,128),128>>>(idx, Af, Ab);
  k_count<<<(int)divup(Ex,128),128>>>(idx);
  k_scan<<<1,1>>>();
  k_fill<<<(int)divup(Nx,64),64>>>(idx, Af, Ab);
  k_transW<<<(int)divup(3*Cx*7*Cx,256),256>>>(gcw);
  k_skprep<<<(int)divup(320*120,256),256>>>(skw, skb);

  float* Xcur = Xa; float* Xnext = Xb;
  int Told = 13;
  const long SKN = 7L*Nx;
  for (int blk=0; blk<3; blk++){
    int Tb = Told-2;
    long TN = (long)Tb*Nx;
    long totd = (long)Bx*Cx*TN;
    k_xmean<<<(int)divup(Bx*Cx*Nx,256),256>>>(Xcur, Told);
    k_escore<<<(int)divup(Bx*Ex,128),128>>>(idx, vsf+blk*Cx, vdf+blk*Cx, vsb+blk*Cx, vdb+blk*Cx);
    k_edge1<<<(int)divup(Bx*EHx,128),128>>>(G0);
    k_edge2<<<(int)divup(Bx*Ex,128),128>>>(G1, wef, web);
    {
      dim3 gr(Bx, Tb, (unsigned)divup(Nx,64));
      k_dconv2<<<gr,256>>>(Xcur, Told, fw+blk*Cx*Cx*2, fb+blk*Cx,
                           gw+blk*Cx*Cx*2, gb+blk*Cx, Tb);
    }
    k_shop2<<<(int)divup(totd,256),256>>>(Tb, 0, 40, 0, 120);
    k_shop2<<<(int)divup(totd,256),256>>>(Tb, 40, 80, 120, 160);
    { // fused adp hops: [x@ADP | x@ADP2] in one GEMM
      dim3 gr((unsigned)divup(1000,128),(unsigned)divup(Cx*Tb,128),Bx);
      k_gemm128<<<gr,256>>>(H, ADPC, H+200*TN, Cx*Tb, 1000, Nx,
                            7*Cx*TN, 0, 7*Cx*TN, 1000, 0,0,0,0,0,
                            H+240*TN, 500);
    }
    {
      dim3 gr((unsigned)divup(TN,128),1,Bx);
      k_gconv<<<gr,256>>>(WT+blk*Cx*7*Cx, G, (int)TN, gcb+blk*Cx, H);
    }
    { dim3 gs(Cx,16); k_bnstats1<<<gs,256>>>(G, Tb); }
    k_bnstats2<<<1,64>>>(Tb);
    k_bnapply1<<<(int)divup(totd,256),256>>>(G, Xcur, Told, Xnext, Tb, bgg+blk*Cx, bgb+blk*Cx);
    { dim3 gs(Cx,16); k_bnstats1<<<gs,256>>>(Xnext, Tb); }
    k_bnstats2<<<1,64>>>(Tb);
    k_bnapply2<<<(int)divup(totd,256),256>>>(Xnext, Tb, bng+blk*Cx, bnb+blk*Cx, blk);
    float* tmp = Xcur; Xcur = Xnext; Xnext = tmp;
    Told = Tb;
  }
  { // fused skip: leaky( SKW @ SK + SKB ), K=120
    dim3 gr((unsigned)divup(SKN,128),(unsigned)divup(320,128),Bx);
    k_gemm128<<<gr,256>>>(SKW, SK, S1, 320, (int)SKN, 120,
                          0, 120L*SKN, 320L*SKN, (int)SKN, SKB, 0,0,0, 1, 0,0);
  }
  { // end1
    dim3 gr((unsigned)divup(SKN,128),(unsigned)divup(640,128),Bx);
    k_gemm128<<<gr,256>>>(e1w, S1, E1, 640, (int)SKN, 320,
                          0, 320L*SKN, 640L*SKN, (int)SKN, e1b, 0,0,0, 1, 0,0);
  }
  k_end2<<<dim3(Bx,7),256>>>(e2w, e2b, out);
}